// round 14
// baseline (speedup 1.0000x reference)
#include <cuda_runtime.h>
#include <cuda.h>
#include <cuda_bf16.h>
#include <cstdint>

// ============================================================
// Problem constants
// ============================================================
constexpr int N_ROWS = 4096;
constexpr int D_DIM  = 768;
constexpr float INV_T = 20.0f;   // 1 / 0.05

constexpr int BM = 128;          // anchor rows per CTA
constexpr int BK = 64;           // K chunk (64 bf16 = 128B = SW128 row)
constexpr int MT = N_ROWS / BM;  // 32
constexpr int NKC = D_DIM / BK;  // 12
constexpr int THREADS = 512;     // 16 warps
constexpr int STAGES = 4;        // slots; prefetch distance = 3
constexpr int PDIST = 3;

constexpr int N_FULL_TILES = 444;   // 3 x 148 SMs, exactly 3 waves
constexpr int N_TAIL_CTAS  = 136;   // (512-444) tiles x 2 N-halves
constexpr int GRID_ALL = N_FULL_TILES + N_TAIL_CTAS;  // 580

constexpr int NP = 32;           // 128-col partial strips
constexpr int A_BYTES = BM * 128;   // 16384
constexpr int SMEM_FULL = 1024 + STAGES * (A_BYTES + 256 * 128);  // 197632

constexpr int CONV_GRID = 1184;  // 148 SMs x 8 blocks: exactly one wave

// ============================================================
// Device scratch (static — no allocation)
// ============================================================
__device__ __nv_bfloat16 g_A[N_ROWS * D_DIM];
__device__ __nv_bfloat16 g_B[N_ROWS * D_DIM];
__device__ float g_partials[NP * N_ROWS];
__device__ float g_last[N_ROWS];
__device__ int   g_done;   // zero-init; self-resetting each run

// ============================================================
// Helpers
// ============================================================
__device__ __forceinline__ uint32_t smem_to_u32(const void* smem_ptr) {
    uint32_t addr;
    asm("{ .reg .u64 tmp; cvta.to.shared.u64 tmp, %1; cvt.u32.u64 %0, tmp; }"
        : "=r"(addr) : "l"(smem_ptr));
    return addr;
}

__device__ __forceinline__ uint32_t sw128(uint32_t off) {
    return off ^ ((off >> 3) & 0x70);
}

__device__ __forceinline__ uint32_t bf2_bits(__nv_bfloat162 v) {
    union { __nv_bfloat162 b; uint32_t u; } cvt;
    cvt.b = v;
    return cvt.u;
}

__device__ __forceinline__ void ldmatrix_x4(uint32_t* r, uint32_t addr) {
    asm volatile("ldmatrix.sync.aligned.m8n8.x4.shared.b16 {%0,%1,%2,%3}, [%4];"
                 : "=r"(r[0]), "=r"(r[1]), "=r"(r[2]), "=r"(r[3]) : "r"(addr));
}

__device__ __forceinline__ void mma16816(float* c, const uint32_t* a,
                                         const uint32_t* b) {
    asm volatile(
        "mma.sync.aligned.m16n8k16.row.col.f32.bf16.bf16.f32 "
        "{%0,%1,%2,%3}, {%4,%5,%6,%7}, {%8,%9}, {%0,%1,%2,%3};"
        : "+f"(c[0]), "+f"(c[1]), "+f"(c[2]), "+f"(c[3])
        : "r"(a[0]), "r"(a[1]), "r"(a[2]), "r"(a[3]), "r"(b[0]), "r"(b[1]));
}

#define MBARRIER_INIT(mbar, count) \
    asm volatile("mbarrier.init.shared.b64 [%0], %1;" \
                 :: "r"((uint32_t)(mbar)), "r"((uint32_t)(count)) : "memory")

#define MBARRIER_EXPECT_TX(mbar, bytes) \
    asm volatile("mbarrier.arrive.expect_tx.shared.b64 _, [%0], %1;" \
                 :: "r"((uint32_t)(mbar)), "r"((uint32_t)(bytes)) : "memory")

#define MBARRIER_ARRIVE(mbar) \
    asm volatile("mbarrier.arrive.shared.b64 _, [%0];" \
                 :: "r"((uint32_t)(mbar)) : "memory")

#define MBARRIER_WAIT_PARITY(mbar, parity) do { \
    uint32_t _mbar = (uint32_t)(mbar); \
    uint32_t _parity = (uint32_t)(parity); \
    uint32_t _done; \
    asm volatile( \
        "{\n\t" \
        ".reg .pred p;\n\t" \
        "mbarrier.try_wait.parity.acquire.cta.shared::cta.b64 p, [%1], %2;\n\t" \
        "selp.b32 %0, 1, 0, p;\n\t" \
        "}" \
        : "=r"(_done) : "r"(_mbar), "r"(_parity) : "memory"); \
    if (!_done) { \
        asm volatile( \
            "{\n\t" \
            ".reg .pred P1;\n\t" \
            "WAIT_LOOP_%=:\n\t" \
            "mbarrier.try_wait.parity.acquire.cta.shared::cta.b64 P1, [%0], %1, 0x989680;\n\t" \
            "@P1 bra.uni WAIT_DONE_%=;\n\t" \
            "bra.uni WAIT_LOOP_%=;\n\t" \
            "WAIT_DONE_%=:\n\t" \
            "}" \
            :: "r"(_mbar), "r"(_parity) : "memory"); \
    } \
} while(0)

#define TMA_LOAD_2D(smem_addr, tmap_ptr, cx, cy, mbar) \
    asm volatile( \
        "cp.async.bulk.tensor.2d.shared::cta.global.tile.mbarrier::complete_tx::bytes " \
        "[%0], [%1, {%2, %3}], [%4];" \
        :: "r"((uint32_t)(smem_addr)), "l"(tmap_ptr), \
           "r"((int)(cx)), "r"((int)(cy)), "r"((uint32_t)(mbar)) \
        : "memory")

// ============================================================
// Kernel 1: f32 -> bf16. One full wave (1184 blocks), 2-item
// stride loop, 8 independent 16B loads in flight per thread.
// ============================================================
__global__ void convert_kernel(const float* __restrict__ anchors,
                               const float* __restrict__ positives) {
    constexpr int TOTAL = N_ROWS * D_DIM / 8;   // 16B output chunks: 393216
    constexpr int NTHR = CONV_GRID * 256;       // 303104
    const int t = blockIdx.x * blockDim.x + threadIdx.x;

    #pragma unroll
    for (int k = 0; k < 2; ++k) {
        const int i = t + k * NTHR;
        if (i < TOTAL) {
            float4 a0 = reinterpret_cast<const float4*>(anchors)[2 * i];
            float4 a1 = reinterpret_cast<const float4*>(anchors)[2 * i + 1];
            float4 p0 = reinterpret_cast<const float4*>(positives)[2 * i];
            float4 p1 = reinterpret_cast<const float4*>(positives)[2 * i + 1];
            uint4 va, vp;
            va.x = bf2_bits(__floats2bfloat162_rn(a0.x, a0.y));
            va.y = bf2_bits(__floats2bfloat162_rn(a0.z, a0.w));
            va.z = bf2_bits(__floats2bfloat162_rn(a1.x, a1.y));
            va.w = bf2_bits(__floats2bfloat162_rn(a1.z, a1.w));
            vp.x = bf2_bits(__floats2bfloat162_rn(p0.x, p0.y));
            vp.y = bf2_bits(__floats2bfloat162_rn(p0.z, p0.w));
            vp.z = bf2_bits(__floats2bfloat162_rn(p1.x, p1.y));
            vp.w = bf2_bits(__floats2bfloat162_rn(p1.z, p1.w));
            reinterpret_cast<uint4*>(g_A)[i] = va;
            reinterpret_cast<uint4*>(g_B)[i] = vp;
        }
    }
}

// ============================================================
// GEMM body (device, templated): TMA-fed bf16 HMMA + fused exp-rowsum.
// NI = n8-MMAs per warp band (8 -> BN=256 full tile, 4 -> BN=128 half).
// SMEM map: [0,96) mbarriers, [512,516) finalize flag, tiles from 1024.
// ============================================================
template <int NI>
__device__ __forceinline__ void gemm_body(
    const CUtensorMap* tmA, const CUtensorMap* tmB, int mt, int col_base) {
    constexpr int B_BYTES_T = NI * 32 * 128;    // 32768 or 16384
    constexpr int STAGE_T = A_BYTES + B_BYTES_T;
    constexpr int NS = NI / 4;                  // 128-col strips per tile

    extern __shared__ char smem[];
    const int tid = threadIdx.x;
    const int lane = tid & 31;
    const int wid = tid >> 5;
    const int warpM = wid & 3;   // 0..3 -> 32-row band
    const int warpN = wid >> 2;  // 0..3 -> (NI*8)-col band
    const uint32_t sb = smem_to_u32(smem);

    auto full_bar  = [&](int s) { return sb + s * 8; };
    auto empty_bar = [&](int s) { return sb + 64 + s * 8; };
    auto stage_off = [&](int s) { return sb + 1024 + (uint32_t)s * STAGE_T; };

    if (tid == 0) {
        #pragma unroll
        for (int s = 0; s < STAGES; ++s) {
            MBARRIER_INIT(full_bar(s), 1);
            MBARRIER_INIT(empty_bar(s), 16);   // one arrive per warp
        }
        asm volatile("fence.proxy.async.shared::cta;" ::: "memory");
    }
    __syncthreads();

    // Prologue: fill first PDIST chunks (slots 0..2)
    if (tid == 0) {
        #pragma unroll
        for (int s = 0; s < PDIST; ++s) {
            MBARRIER_EXPECT_TX(full_bar(s), STAGE_T);
            TMA_LOAD_2D(stage_off(s),           tmA, s * BK, mt * BM, full_bar(s));
            TMA_LOAD_2D(stage_off(s) + A_BYTES, tmB, s * BK, col_base, full_bar(s));
        }
    }

    float acc[2 * NI][4];
    #pragma unroll
    for (int i = 0; i < 2 * NI; ++i)
        #pragma unroll
        for (int j = 0; j < 4; ++j) acc[i][j] = 0.0f;

    const uint32_t a_row = (uint32_t)(warpM * 32 + (lane & 15));
    const uint32_t a_kb  = (uint32_t)((lane >> 4) * 16);
    const uint32_t b_row = (uint32_t)(warpN * (NI * 8) +
                                      ((lane & 7) | ((lane >> 4) << 3)));
    const uint32_t b_kb  = (uint32_t)(((lane >> 3) & 1) * 16);

    for (int c = 0; c < NKC; ++c) {
        const int s = c & (STAGES - 1);
        MBARRIER_WAIT_PARITY(full_bar(s), (c / STAGES) & 1);

        const uint32_t sA = stage_off(s);
        const uint32_t sB = sA + A_BYTES;

        #pragma unroll
        for (int ks = 0; ks < 4; ++ks) {
            uint32_t a[2][4];
            #pragma unroll
            for (int mi = 0; mi < 2; ++mi) {
                uint32_t off = (a_row + mi * 16) * 128 + ks * 32 + a_kb;
                ldmatrix_x4(a[mi], sA + sw128(off));
            }
            uint32_t b[NI / 2][4];
            #pragma unroll
            for (int np = 0; np < NI / 2; ++np) {
                uint32_t off = (b_row + np * 16) * 128 + ks * 32 + b_kb;
                ldmatrix_x4(b[np], sB + sw128(off));
            }
            #pragma unroll
            for (int mi = 0; mi < 2; ++mi)
                #pragma unroll
                for (int ni = 0; ni < NI; ++ni)
                    mma16816(acc[mi * NI + ni], a[mi], &b[ni >> 1][(ni & 1) * 2]);
        }

        if (lane == 0) MBARRIER_ARRIVE(empty_bar(s));

        if (tid == 0) {
            const int q = c + PDIST;
            if (q < NKC) {
                const int sq = q & (STAGES - 1);
                if (c >= 1)
                    MBARRIER_WAIT_PARITY(empty_bar(sq), ((c - 1) / STAGES) & 1);
                MBARRIER_EXPECT_TX(full_bar(sq), STAGE_T);
                TMA_LOAD_2D(stage_off(sq),           tmA, q * BK, mt * BM,
                            full_bar(sq));
                TMA_LOAD_2D(stage_off(sq) + A_BYTES, tmB, q * BK, col_base,
                            full_bar(sq));
            }
        }
    }

    // ---- Fused epilogue: exp, diagonal, last-col, strip rowsums ----
    __syncthreads();
    float* rowsum = reinterpret_cast<float*>(smem + 1024);  // NS*128 floats
    if (tid < NS * 128) rowsum[tid] = 0.0f;
    __syncthreads();

    const int sidx = (warpN * (NI * 8)) >> 7;   // strip within tile

    #pragma unroll
    for (int mi = 0; mi < 2; ++mi) {
        #pragma unroll
        for (int h = 0; h < 2; ++h) {
            const int lr = warpM * 32 + mi * 16 + h * 8 + (lane >> 2);
            const int grow = mt * BM + lr;
            float rs = 0.0f;
            #pragma unroll
            for (int ni = 0; ni < NI; ++ni) {
                #pragma unroll
                for (int j = 0; j < 2; ++j) {
                    float v = acc[mi * NI + ni][h * 2 + j] * INV_T;
                    int gcol = col_base + warpN * (NI * 8) + ni * 8 +
                               (lane & 3) * 2 + j;
                    float e = __expf(v);
                    rs += e;
                    if (gcol == grow) rs += e;           // diagonal double-count
                    if (gcol == N_ROWS - 1) g_last[grow] = v;
                }
            }
            rs += __shfl_xor_sync(0xFFFFFFFF, rs, 1);
            rs += __shfl_xor_sync(0xFFFFFFFF, rs, 2);
            if ((lane & 3) == 0) atomicAdd(&rowsum[sidx * 128 + lr], rs);
        }
    }
    __syncthreads();
    if (tid < NS * 128) {
        const int st = col_base / 128 + (tid >> 7);
        g_partials[st * N_ROWS + mt * BM + (tid & 127)] = rowsum[tid];
    }
}

// ============================================================
// Kernel 2: merged GEMM + last-CTA finalize.
// 444 full tiles then 136 half-tiles; the last CTA to finish its
// epilogue runs the deterministic row-loss reduction inline.
// ============================================================
__global__ void __launch_bounds__(THREADS, 1)
gemm_all_kernel(const __grid_constant__ CUtensorMap tmA,
                const __grid_constant__ CUtensorMap tmB256,
                const __grid_constant__ CUtensorMap tmB128,
                float* __restrict__ out) {
    extern __shared__ char smem[];
    const int bid = blockIdx.x;
    const int tid = threadIdx.x;

    if (bid < N_FULL_TILES) {
        const int mt = bid & (MT - 1);
        const int col_base = (bid >> 5) * 256;
        gemm_body<8>(&tmA, &tmB256, mt, col_base);
    } else {
        const int tb = bid - N_FULL_TILES;
        const int u = N_FULL_TILES + (tb >> 1);
        const int mt = u & (MT - 1);
        const int col_base = (u >> 5) * 256 + (tb & 1) * 128;
        gemm_body<4>(&tmA, &tmB128, mt, col_base);
    }

    // ---- Last-CTA finalize (threadfence-reduction pattern) ----
    // Flag lives in dynamic smem (offset 512, unused by gemm_body).
    int* is_last = reinterpret_cast<int*>(smem + 512);
    __syncthreads();
    __threadfence();                      // publish partials/last
    if (tid == 0) {
        int old = atomicAdd(&g_done, 1);
        *is_last = (old == GRID_ALL - 1);
    }
    __syncthreads();
    if (!*is_last) return;
    __threadfence();                      // acquire all partials

    float* red = reinterpret_cast<float*>(smem + 1024);   // reuse tile smem
    float acc = 0.0f;
    #pragma unroll
    for (int k = 0; k < N_ROWS / THREADS; ++k) {   // 8 rows per thread
        const int r = tid + k * THREADS;
        float denom = 0.0f;
        #pragma unroll
        for (int n = 0; n < NP; ++n)
            denom += g_partials[n * N_ROWS + r];
        acc += logf(denom) - g_last[r];            // loss_r
    }
    red[tid] = acc;
    __syncthreads();
    #pragma unroll
    for (int s = 256; s > 0; s >>= 1) {
        if (tid < s) red[tid] += red[tid + s];
        __syncthreads();
    }
    if (tid == 0) {
        out[0] = red[0];
        g_done = 0;                                // reset for next replay
    }
}

// ============================================================
// Launch
// ============================================================
typedef CUresult (*EncodeTiledFn)(
    CUtensorMap*, CUtensorMapDataType, cuuint32_t, void*,
    const cuuint64_t*, const cuuint64_t*, const cuuint32_t*, const cuuint32_t*,
    CUtensorMapInterleave, CUtensorMapSwizzle, CUtensorMapL2promotion,
    CUtensorMapFloatOOBfill);

extern "C" void kernel_launch(void* const* d_in, const int* in_sizes, int n_in,
                              void* d_out, int out_size) {
    const float* anchors   = (const float*)d_in[0];
    const float* positives = (const float*)d_in[1];
    float* out = (float*)d_out;

    void* fn = nullptr;
    cudaDriverEntryPointQueryResult qr;
    cudaGetDriverEntryPointByVersion("cuTensorMapEncodeTiled", &fn, 12000,
                                     cudaEnableDefault, &qr);
    EncodeTiledFn encode = (EncodeTiledFn)fn;

    void* pA = nullptr;
    void* pB = nullptr;
    cudaGetSymbolAddress(&pA, g_A);
    cudaGetSymbolAddress(&pB, g_B);

    CUtensorMap tmA, tmB256, tmB128;
    cuuint64_t dims[2]    = {(cuuint64_t)D_DIM, (cuuint64_t)N_ROWS};
    cuuint64_t strides[1] = {(cuuint64_t)D_DIM * sizeof(__nv_bfloat16)};
    cuuint32_t es[2]      = {1, 1};
    cuuint32_t boxA[2]    = {(cuuint32_t)BK, (cuuint32_t)BM};
    cuuint32_t boxB256[2] = {(cuuint32_t)BK, 256};
    cuuint32_t boxB128[2] = {(cuuint32_t)BK, 128};
    encode(&tmA, CU_TENSOR_MAP_DATA_TYPE_BFLOAT16, 2, pA, dims, strides, boxA,
           es, CU_TENSOR_MAP_INTERLEAVE_NONE, CU_TENSOR_MAP_SWIZZLE_128B,
           CU_TENSOR_MAP_L2_PROMOTION_L2_128B, CU_TENSOR_MAP_FLOAT_OOB_FILL_NONE);
    encode(&tmB256, CU_TENSOR_MAP_DATA_TYPE_BFLOAT16, 2, pB, dims, strides,
           boxB256, es, CU_TENSOR_MAP_INTERLEAVE_NONE, CU_TENSOR_MAP_SWIZZLE_128B,
           CU_TENSOR_MAP_L2_PROMOTION_L2_128B, CU_TENSOR_MAP_FLOAT_OOB_FILL_NONE);
    encode(&tmB128, CU_TENSOR_MAP_DATA_TYPE_BFLOAT16, 2, pB, dims, strides,
           boxB128, es, CU_TENSOR_MAP_INTERLEAVE_NONE, CU_TENSOR_MAP_SWIZZLE_128B,
           CU_TENSOR_MAP_L2_PROMOTION_L2_128B, CU_TENSOR_MAP_FLOAT_OOB_FILL_NONE);

    cudaFuncSetAttribute(gemm_all_kernel,
                         cudaFuncAttributeMaxDynamicSharedMemorySize, SMEM_FULL);

    convert_kernel<<<CONV_GRID, 256>>>(anchors, positives);

    gemm_all_kernel<<<GRID_ALL, THREADS, SMEM_FULL>>>(tmA, tmB256, tmB128, out);
}

// round 15
// speedup vs baseline: 1.0844x; 1.0844x over previous
#include <cuda_runtime.h>
#include <cuda.h>
#include <cuda_bf16.h>
#include <cstdint>

// ============================================================
// Problem constants
// ============================================================
constexpr int N_ROWS = 4096;
constexpr int D_DIM  = 768;
constexpr float INV_T = 20.0f;   // 1 / 0.05

constexpr int BM = 128;          // anchor rows per CTA
constexpr int BK = 64;           // K chunk (64 bf16 = 128B = SW128 row)
constexpr int MT = N_ROWS / BM;  // 32
constexpr int NKC = D_DIM / BK;  // 12
constexpr int THREADS = 512;     // 16 warps
constexpr int STAGES = 4;        // slots; prefetch distance = 3
constexpr int PDIST = 3;

constexpr int N_FULL_TILES = 444;   // 3 x 148 SMs, exactly 3 waves
constexpr int N_TAIL_CTAS  = 136;   // (512-444) tiles x 2 N-halves
constexpr int GRID_ALL = N_FULL_TILES + N_TAIL_CTAS;  // 580

constexpr int NP = 32;           // 128-col partial strips
constexpr int A_BYTES = BM * 128;   // 16384
constexpr int SMEM_FULL = 1024 + STAGES * (A_BYTES + 256 * 128);  // 197632

constexpr int CONV_GRID = 768;   // all co-resident; exactly 2 items/thread

// ============================================================
// Device scratch (static — no allocation)
// ============================================================
__device__ __nv_bfloat16 g_A[N_ROWS * D_DIM];
__device__ __nv_bfloat16 g_B[N_ROWS * D_DIM];
__device__ float g_partials[NP * N_ROWS];
__device__ float g_last[N_ROWS];
__device__ float g_block_loss[32];
__device__ int   g_ctr;   // zero-init; self-resetting

// ============================================================
// Helpers
// ============================================================
__device__ __forceinline__ uint32_t smem_to_u32(const void* smem_ptr) {
    uint32_t addr;
    asm("{ .reg .u64 tmp; cvta.to.shared.u64 tmp, %1; cvt.u32.u64 %0, tmp; }"
        : "=r"(addr) : "l"(smem_ptr));
    return addr;
}

__device__ __forceinline__ uint32_t sw128(uint32_t off) {
    return off ^ ((off >> 3) & 0x70);
}

__device__ __forceinline__ uint32_t bf2_bits(__nv_bfloat162 v) {
    union { __nv_bfloat162 b; uint32_t u; } cvt;
    cvt.b = v;
    return cvt.u;
}

__device__ __forceinline__ void ldmatrix_x4(uint32_t* r, uint32_t addr) {
    asm volatile("ldmatrix.sync.aligned.m8n8.x4.shared.b16 {%0,%1,%2,%3}, [%4];"
                 : "=r"(r[0]), "=r"(r[1]), "=r"(r[2]), "=r"(r[3]) : "r"(addr));
}

__device__ __forceinline__ void mma16816(float* c, const uint32_t* a,
                                         const uint32_t* b) {
    asm volatile(
        "mma.sync.aligned.m16n8k16.row.col.f32.bf16.bf16.f32 "
        "{%0,%1,%2,%3}, {%4,%5,%6,%7}, {%8,%9}, {%0,%1,%2,%3};"
        : "+f"(c[0]), "+f"(c[1]), "+f"(c[2]), "+f"(c[3])
        : "r"(a[0]), "r"(a[1]), "r"(a[2]), "r"(a[3]), "r"(b[0]), "r"(b[1]));
}

#define MBARRIER_INIT(mbar, count) \
    asm volatile("mbarrier.init.shared.b64 [%0], %1;" \
                 :: "r"((uint32_t)(mbar)), "r"((uint32_t)(count)) : "memory")

#define MBARRIER_EXPECT_TX(mbar, bytes) \
    asm volatile("mbarrier.arrive.expect_tx.shared.b64 _, [%0], %1;" \
                 :: "r"((uint32_t)(mbar)), "r"((uint32_t)(bytes)) : "memory")

#define MBARRIER_ARRIVE(mbar) \
    asm volatile("mbarrier.arrive.shared.b64 _, [%0];" \
                 :: "r"((uint32_t)(mbar)) : "memory")

#define MBARRIER_WAIT_PARITY(mbar, parity) do { \
    uint32_t _mbar = (uint32_t)(mbar); \
    uint32_t _parity = (uint32_t)(parity); \
    uint32_t _done; \
    asm volatile( \
        "{\n\t" \
        ".reg .pred p;\n\t" \
        "mbarrier.try_wait.parity.acquire.cta.shared::cta.b64 p, [%1], %2;\n\t" \
        "selp.b32 %0, 1, 0, p;\n\t" \
        "}" \
        : "=r"(_done) : "r"(_mbar), "r"(_parity) : "memory"); \
    if (!_done) { \
        asm volatile( \
            "{\n\t" \
            ".reg .pred P1;\n\t" \
            "WAIT_LOOP_%=:\n\t" \
            "mbarrier.try_wait.parity.acquire.cta.shared::cta.b64 P1, [%0], %1, 0x989680;\n\t" \
            "@P1 bra.uni WAIT_DONE_%=;\n\t" \
            "bra.uni WAIT_LOOP_%=;\n\t" \
            "WAIT_DONE_%=:\n\t" \
            "}" \
            :: "r"(_mbar), "r"(_parity) : "memory"); \
    } \
} while(0)

#define TMA_LOAD_2D(smem_addr, tmap_ptr, cx, cy, mbar) \
    asm volatile( \
        "cp.async.bulk.tensor.2d.shared::cta.global.tile.mbarrier::complete_tx::bytes " \
        "[%0], [%1, {%2, %3}], [%4];" \
        :: "r"((uint32_t)(smem_addr)), "l"(tmap_ptr), \
           "r"((int)(cx)), "r"((int)(cy)), "r"((uint32_t)(mbar)) \
        : "memory")

// ============================================================
// Kernel 1: f32 -> bf16. 768 blocks (all co-resident), exactly
// 2 items/thread, 8 independent 16B loads in flight per thread.
// ============================================================
__global__ void convert_kernel(const float* __restrict__ anchors,
                               const float* __restrict__ positives) {
    constexpr int NTHR = CONV_GRID * 256;       // 196608
    const int t = blockIdx.x * blockDim.x + threadIdx.x;
    const int i0 = t;
    const int i1 = t + NTHR;

    float4 a00 = reinterpret_cast<const float4*>(anchors)[2 * i0];
    float4 a01 = reinterpret_cast<const float4*>(anchors)[2 * i0 + 1];
    float4 p00 = reinterpret_cast<const float4*>(positives)[2 * i0];
    float4 p01 = reinterpret_cast<const float4*>(positives)[2 * i0 + 1];
    float4 a10 = reinterpret_cast<const float4*>(anchors)[2 * i1];
    float4 a11 = reinterpret_cast<const float4*>(anchors)[2 * i1 + 1];
    float4 p10 = reinterpret_cast<const float4*>(positives)[2 * i1];
    float4 p11 = reinterpret_cast<const float4*>(positives)[2 * i1 + 1];

    uint4 v;
    v.x = bf2_bits(__floats2bfloat162_rn(a00.x, a00.y));
    v.y = bf2_bits(__floats2bfloat162_rn(a00.z, a00.w));
    v.z = bf2_bits(__floats2bfloat162_rn(a01.x, a01.y));
    v.w = bf2_bits(__floats2bfloat162_rn(a01.z, a01.w));
    reinterpret_cast<uint4*>(g_A)[i0] = v;
    v.x = bf2_bits(__floats2bfloat162_rn(p00.x, p00.y));
    v.y = bf2_bits(__floats2bfloat162_rn(p00.z, p00.w));
    v.z = bf2_bits(__floats2bfloat162_rn(p01.x, p01.y));
    v.w = bf2_bits(__floats2bfloat162_rn(p01.z, p01.w));
    reinterpret_cast<uint4*>(g_B)[i0] = v;
    v.x = bf2_bits(__floats2bfloat162_rn(a10.x, a10.y));
    v.y = bf2_bits(__floats2bfloat162_rn(a10.z, a10.w));
    v.z = bf2_bits(__floats2bfloat162_rn(a11.x, a11.y));
    v.w = bf2_bits(__floats2bfloat162_rn(a11.z, a11.w));
    reinterpret_cast<uint4*>(g_A)[i1] = v;
    v.x = bf2_bits(__floats2bfloat162_rn(p10.x, p10.y));
    v.y = bf2_bits(__floats2bfloat162_rn(p10.z, p10.w));
    v.z = bf2_bits(__floats2bfloat162_rn(p11.x, p11.y));
    v.w = bf2_bits(__floats2bfloat162_rn(p11.z, p11.w));
    reinterpret_cast<uint4*>(g_B)[i1] = v;
}

// ============================================================
// GEMM body (device, templated): TMA-fed bf16 HMMA + fused exp-rowsum.
// NI = n8-MMAs per warp band (8 -> BN=256 full tile, 4 -> BN=128 half).
// ============================================================
template <int NI>
__device__ __forceinline__ void gemm_body(
    const CUtensorMap* tmA, const CUtensorMap* tmB, int mt, int col_base) {
    constexpr int B_BYTES_T = NI * 32 * 128;    // 32768 or 16384
    constexpr int STAGE_T = A_BYTES + B_BYTES_T;
    constexpr int NS = NI / 4;                  // 128-col strips per tile

    extern __shared__ char smem[];
    const int tid = threadIdx.x;
    const int lane = tid & 31;
    const int wid = tid >> 5;
    const int warpM = wid & 3;   // 0..3 -> 32-row band
    const int warpN = wid >> 2;  // 0..3 -> (NI*8)-col band
    const uint32_t sb = smem_to_u32(smem);

    auto full_bar  = [&](int s) { return sb + s * 8; };
    auto empty_bar = [&](int s) { return sb + 64 + s * 8; };
    auto stage_off = [&](int s) { return sb + 1024 + (uint32_t)s * STAGE_T; };

    if (tid == 0) {
        #pragma unroll
        for (int s = 0; s < STAGES; ++s) {
            MBARRIER_INIT(full_bar(s), 1);
            MBARRIER_INIT(empty_bar(s), 16);   // one arrive per warp
        }
        asm volatile("fence.proxy.async.shared::cta;" ::: "memory");
    }
    __syncthreads();

    // Prologue: fill first PDIST chunks (slots 0..2)
    if (tid == 0) {
        #pragma unroll
        for (int s = 0; s < PDIST; ++s) {
            MBARRIER_EXPECT_TX(full_bar(s), STAGE_T);
            TMA_LOAD_2D(stage_off(s),           tmA, s * BK, mt * BM, full_bar(s));
            TMA_LOAD_2D(stage_off(s) + A_BYTES, tmB, s * BK, col_base, full_bar(s));
        }
    }

    float acc[2 * NI][4];
    #pragma unroll
    for (int i = 0; i < 2 * NI; ++i)
        #pragma unroll
        for (int j = 0; j < 4; ++j) acc[i][j] = 0.0f;

    const uint32_t a_row = (uint32_t)(warpM * 32 + (lane & 15));
    const uint32_t a_kb  = (uint32_t)((lane >> 4) * 16);
    const uint32_t b_row = (uint32_t)(warpN * (NI * 8) +
                                      ((lane & 7) | ((lane >> 4) << 3)));
    const uint32_t b_kb  = (uint32_t)(((lane >> 3) & 1) * 16);

    for (int c = 0; c < NKC; ++c) {
        const int s = c & (STAGES - 1);
        MBARRIER_WAIT_PARITY(full_bar(s), (c / STAGES) & 1);

        const uint32_t sA = stage_off(s);
        const uint32_t sB = sA + A_BYTES;

        #pragma unroll
        for (int ks = 0; ks < 4; ++ks) {
            uint32_t a[2][4];
            #pragma unroll
            for (int mi = 0; mi < 2; ++mi) {
                uint32_t off = (a_row + mi * 16) * 128 + ks * 32 + a_kb;
                ldmatrix_x4(a[mi], sA + sw128(off));
            }
            uint32_t b[NI / 2][4];
            #pragma unroll
            for (int np = 0; np < NI / 2; ++np) {
                uint32_t off = (b_row + np * 16) * 128 + ks * 32 + b_kb;
                ldmatrix_x4(b[np], sB + sw128(off));
            }
            #pragma unroll
            for (int mi = 0; mi < 2; ++mi)
                #pragma unroll
                for (int ni = 0; ni < NI; ++ni)
                    mma16816(acc[mi * NI + ni], a[mi], &b[ni >> 1][(ni & 1) * 2]);
        }

        if (lane == 0) MBARRIER_ARRIVE(empty_bar(s));

        if (tid == 0) {
            const int q = c + PDIST;
            if (q < NKC) {
                const int sq = q & (STAGES - 1);
                if (c >= 1)
                    MBARRIER_WAIT_PARITY(empty_bar(sq), ((c - 1) / STAGES) & 1);
                MBARRIER_EXPECT_TX(full_bar(sq), STAGE_T);
                TMA_LOAD_2D(stage_off(sq),           tmA, q * BK, mt * BM,
                            full_bar(sq));
                TMA_LOAD_2D(stage_off(sq) + A_BYTES, tmB, q * BK, col_base,
                            full_bar(sq));
            }
        }
    }

    // ---- Fused epilogue: exp, diagonal, last-col, strip rowsums ----
    __syncthreads();
    float* rowsum = reinterpret_cast<float*>(smem + 1024);  // NS*128 floats
    if (tid < NS * 128) rowsum[tid] = 0.0f;
    __syncthreads();

    const int sidx = (warpN * (NI * 8)) >> 7;   // strip within tile

    #pragma unroll
    for (int mi = 0; mi < 2; ++mi) {
        #pragma unroll
        for (int h = 0; h < 2; ++h) {
            const int lr = warpM * 32 + mi * 16 + h * 8 + (lane >> 2);
            const int grow = mt * BM + lr;
            float rs = 0.0f;
            #pragma unroll
            for (int ni = 0; ni < NI; ++ni) {
                #pragma unroll
                for (int j = 0; j < 2; ++j) {
                    float v = acc[mi * NI + ni][h * 2 + j] * INV_T;
                    int gcol = col_base + warpN * (NI * 8) + ni * 8 +
                               (lane & 3) * 2 + j;
                    float e = __expf(v);
                    rs += e;
                    if (gcol == grow) rs += e;           // diagonal double-count
                    if (gcol == N_ROWS - 1) g_last[grow] = v;
                }
            }
            rs += __shfl_xor_sync(0xFFFFFFFF, rs, 1);
            rs += __shfl_xor_sync(0xFFFFFFFF, rs, 2);
            if ((lane & 3) == 0) atomicAdd(&rowsum[sidx * 128 + lr], rs);
        }
    }
    __syncthreads();
    if (tid < NS * 128) {
        const int st = col_base / 128 + (tid >> 7);
        g_partials[st * N_ROWS + mt * BM + (tid & 127)] = rowsum[tid];
    }
}

// ============================================================
// Kernel 2: merged GEMM — 444 full tiles then 136 half-tiles.
// ============================================================
__global__ void __launch_bounds__(THREADS, 1)
gemm_all_kernel(const __grid_constant__ CUtensorMap tmA,
                const __grid_constant__ CUtensorMap tmB256,
                const __grid_constant__ CUtensorMap tmB128) {
    const int bid = blockIdx.x;
    if (bid < N_FULL_TILES) {
        const int mt = bid & (MT - 1);
        const int col_base = (bid >> 5) * 256;
        gemm_body<8>(&tmA, &tmB256, mt, col_base);
    } else {
        const int tb = bid - N_FULL_TILES;
        const int u = N_FULL_TILES + (tb >> 1);
        const int mt = u & (MT - 1);
        const int col_base = (u >> 5) * 256 + (tb & 1) * 128;
        gemm_body<4>(&tmA, &tmB128, mt, col_base);
    }
}

// ============================================================
// Kernel 3: parallel deterministic finalize (32 blocks x 128 thr;
// last-arriving block sums the 32 block partials in fixed order)
// ============================================================
__global__ void __launch_bounds__(128)
finalize_kernel(float* __restrict__ out) {
    __shared__ float red[128];
    const int r = blockIdx.x * 128 + threadIdx.x;
    float denom = 0.0f;
    #pragma unroll
    for (int n = 0; n < NP; ++n)
        denom += g_partials[n * N_ROWS + r];
    red[threadIdx.x] = logf(denom) - g_last[r];  // loss_r
    __syncthreads();
    #pragma unroll
    for (int s = 64; s > 0; s >>= 1) {
        if (threadIdx.x < s) red[threadIdx.x] += red[threadIdx.x + s];
        __syncthreads();
    }
    if (threadIdx.x == 0) {
        g_block_loss[blockIdx.x] = red[0];
        __threadfence();
        int old = atomicAdd(&g_ctr, 1);
        if (old == 31) {
            g_ctr = 0;                       // reset for next replay
            volatile float* bl = g_block_loss;
            float acc = 0.0f;
            #pragma unroll
            for (int b = 0; b < 32; ++b) acc += bl[b];
            out[0] = acc;
        }
    }
}

// ============================================================
// Launch
// ============================================================
typedef CUresult (*EncodeTiledFn)(
    CUtensorMap*, CUtensorMapDataType, cuuint32_t, void*,
    const cuuint64_t*, const cuuint64_t*, const cuuint32_t*, const cuuint32_t*,
    CUtensorMapInterleave, CUtensorMapSwizzle, CUtensorMapL2promotion,
    CUtensorMapFloatOOBfill);

extern "C" void kernel_launch(void* const* d_in, const int* in_sizes, int n_in,
                              void* d_out, int out_size) {
    const float* anchors   = (const float*)d_in[0];
    const float* positives = (const float*)d_in[1];
    float* out = (float*)d_out;

    void* fn = nullptr;
    cudaDriverEntryPointQueryResult qr;
    cudaGetDriverEntryPointByVersion("cuTensorMapEncodeTiled", &fn, 12000,
                                     cudaEnableDefault, &qr);
    EncodeTiledFn encode = (EncodeTiledFn)fn;

    void* pA = nullptr;
    void* pB = nullptr;
    cudaGetSymbolAddress(&pA, g_A);
    cudaGetSymbolAddress(&pB, g_B);

    CUtensorMap tmA, tmB256, tmB128;
    cuuint64_t dims[2]    = {(cuuint64_t)D_DIM, (cuuint64_t)N_ROWS};
    cuuint64_t strides[1] = {(cuuint64_t)D_DIM * sizeof(__nv_bfloat16)};
    cuuint32_t es[2]      = {1, 1};
    cuuint32_t boxA[2]    = {(cuuint32_t)BK, (cuuint32_t)BM};
    cuuint32_t boxB256[2] = {(cuuint32_t)BK, 256};
    cuuint32_t boxB128[2] = {(cuuint32_t)BK, 128};
    encode(&tmA, CU_TENSOR_MAP_DATA_TYPE_BFLOAT16, 2, pA, dims, strides, boxA,
           es, CU_TENSOR_MAP_INTERLEAVE_NONE, CU_TENSOR_MAP_SWIZZLE_128B,
           CU_TENSOR_MAP_L2_PROMOTION_L2_128B, CU_TENSOR_MAP_FLOAT_OOB_FILL_NONE);
    encode(&tmB256, CU_TENSOR_MAP_DATA_TYPE_BFLOAT16, 2, pB, dims, strides,
           boxB256, es, CU_TENSOR_MAP_INTERLEAVE_NONE, CU_TENSOR_MAP_SWIZZLE_128B,
           CU_TENSOR_MAP_L2_PROMOTION_L2_128B, CU_TENSOR_MAP_FLOAT_OOB_FILL_NONE);
    encode(&tmB128, CU_TENSOR_MAP_DATA_TYPE_BFLOAT16, 2, pB, dims, strides,
           boxB128, es, CU_TENSOR_MAP_INTERLEAVE_NONE, CU_TENSOR_MAP_SWIZZLE_128B,
           CU_TENSOR_MAP_L2_PROMOTION_L2_128B, CU_TENSOR_MAP_FLOAT_OOB_FILL_NONE);

    cudaFuncSetAttribute(gemm_all_kernel,
                         cudaFuncAttributeMaxDynamicSharedMemorySize, SMEM_FULL);

    convert_kernel<<<CONV_GRID, 256>>>(anchors, positives);

    gemm_all_kernel<<<GRID_ALL, THREADS, SMEM_FULL>>>(tmA, tmB256, tmB128);

    finalize_kernel<<<32, 128>>>(out);
}